// round 2
// baseline (speedup 1.0000x reference)
#include <cuda_runtime.h>
#include <math.h>

// ---------------------------------------------------------------------------
// CT-GRU cell: B=2048, U=512, M=8, D=512, fused=1024
// Round 1: correct fp32 baseline. GEMMs: fused@W_r [1024x4096],
// fused@W_u [1024x4096], reset@W_d [1024x512], all SIMT fp32 128x128x8 tiles.
// ---------------------------------------------------------------------------

#define BB 2048
#define UU 512
#define MM 8
#define DD 512
#define FD 1024
#define RU 4096   // U*M

// scratch (allocation-free device globals)
__device__ float g_fused[(size_t)BB * FD];   // [B, D+U]
__device__ float g_reset[(size_t)BB * FD];   // [B, D+U] (q_input part filled later)
__device__ float g_r[(size_t)BB * RU];       // ln_tau_r
__device__ float g_u[(size_t)BB * RU];       // ln_tau_s
__device__ float g_dpre[(size_t)BB * UU];    // pre-tanh detect

#define LN_TAU_STEP 1.1512925464970229f      // 0.5 * ln(10)

// ---------------------------------------------------------------------------
// prep: h = sum_m h_hat; fused = [inputs, h]; reset[:,:512] = inputs
// ---------------------------------------------------------------------------
__global__ void prep_kernel(const float* __restrict__ inputs,
                            const float* __restrict__ state)
{
    int idx = blockIdx.x * blockDim.x + threadIdx.x;   // b*512 + j
    if (idx >= BB * UU) return;
    int b = idx >> 9;
    int j = idx & 511;

    float x = inputs[(size_t)b * DD + j];
    g_fused[(size_t)b * FD + j] = x;
    g_reset[(size_t)b * FD + j] = x;

    const float* hp = state + (size_t)b * RU + j * MM;
    float4 h0 = *(const float4*)(hp);
    float4 h1 = *(const float4*)(hp + 4);
    float h = ((h0.x + h0.y) + (h0.z + h0.w)) + ((h1.x + h1.y) + (h1.z + h1.w));
    g_fused[(size_t)b * FD + DD + j] = h;
}

// ---------------------------------------------------------------------------
// SGEMM with fused bias: C[M,N] = A[M,K] @ W[K,N] + bias[N]
// 128x128 tile, BK=8, 256 threads, 8x8 per-thread microtile.
// ---------------------------------------------------------------------------
#define BM 128
#define BN 128
#define BK 8

__global__ void __launch_bounds__(256)
sgemm_bias_kernel(const float* __restrict__ A,
                  const float* __restrict__ W,
                  const float* __restrict__ bias,
                  float* __restrict__ C,
                  int Mdim, int Ndim, int Kdim)
{
    __shared__ float As[BK][BM];
    __shared__ float Bs[BK][BN];

    const int tid = threadIdx.x;
    const int tx = tid & 15;          // 0..15 -> col group
    const int ty = tid >> 4;          // 0..15 -> row group
    const int bm = blockIdx.y * BM;
    const int bn = blockIdx.x * BN;

    // A tile loader: one float4 per thread (128 rows x 8 cols)
    const int aRow = tid >> 1;             // 0..127
    const int aCol = (tid & 1) * 4;        // 0 or 4
    // B tile loader: one float4 per thread (8 rows x 128 cols)
    const int bRow = tid >> 5;             // 0..7
    const int bCol = (tid & 31) * 4;       // 0..124

    const float* Aptr = A + (size_t)(bm + aRow) * Kdim + aCol;
    const float* Wptr = W + (size_t)bRow * Ndim + bn + bCol;

    float acc[8][8];
#pragma unroll
    for (int i = 0; i < 8; i++)
#pragma unroll
        for (int j = 0; j < 8; j++) acc[i][j] = 0.0f;

    for (int k0 = 0; k0 < Kdim; k0 += BK) {
        float4 av = *(const float4*)(Aptr + k0);
        As[aCol + 0][aRow] = av.x;
        As[aCol + 1][aRow] = av.y;
        As[aCol + 2][aRow] = av.z;
        As[aCol + 3][aRow] = av.w;
        *(float4*)&Bs[bRow][bCol] = *(const float4*)(Wptr + (size_t)k0 * Ndim);
        __syncthreads();

#pragma unroll
        for (int k = 0; k < BK; ++k) {
            float a[8], bv[8];
            *(float4*)&a[0]  = *(const float4*)&As[k][ty * 8];
            *(float4*)&a[4]  = *(const float4*)&As[k][ty * 8 + 4];
            *(float4*)&bv[0] = *(const float4*)&Bs[k][tx * 8];
            *(float4*)&bv[4] = *(const float4*)&Bs[k][tx * 8 + 4];
#pragma unroll
            for (int i = 0; i < 8; i++)
#pragma unroll
                for (int j = 0; j < 8; j++)
                    acc[i][j] = fmaf(a[i], bv[j], acc[i][j]);
        }
        __syncthreads();
    }

    // epilogue with bias
    float bsv[8];
#pragma unroll
    for (int j = 0; j < 8; j++) bsv[j] = bias[bn + tx * 8 + j];

#pragma unroll
    for (int i = 0; i < 8; i++) {
        const int row = bm + ty * 8 + i;
        float4 v0, v1;
        v0.x = acc[i][0] + bsv[0]; v0.y = acc[i][1] + bsv[1];
        v0.z = acc[i][2] + bsv[2]; v0.w = acc[i][3] + bsv[3];
        v1.x = acc[i][4] + bsv[4]; v1.y = acc[i][5] + bsv[5];
        v1.z = acc[i][6] + bsv[6]; v1.w = acc[i][7] + bsv[7];
        *(float4*)&C[(size_t)row * Ndim + bn + tx * 8]     = v0;
        *(float4*)&C[(size_t)row * Ndim + bn + tx * 8 + 4] = v1;
    }
}

// ---------------------------------------------------------------------------
// gate_r: rki = softmax_m(-(ln_tau_r - table)^2); q = sum rki*h_hat
// writes q into reset[:, 512+u]
// ---------------------------------------------------------------------------
__global__ void gate_r_kernel(const float* __restrict__ state)
{
    int idx = blockIdx.x * blockDim.x + threadIdx.x;   // b*U + u
    if (idx >= BB * UU) return;
    int b = idx >> 9;
    int u = idx & 511;

    const float* rp = g_r + (size_t)b * RU + u * MM;
    float x[8];
    *(float4*)&x[0] = *(const float4*)(rp);
    *(float4*)&x[4] = *(const float4*)(rp + 4);

    const float* hp = state + (size_t)b * RU + u * MM;
    float h[8];
    *(float4*)&h[0] = *(const float4*)(hp);
    *(float4*)&h[4] = *(const float4*)(hp + 4);

    float e[8], mx = -1e30f;
#pragma unroll
    for (int m = 0; m < 8; m++) {
        float d = x[m] - LN_TAU_STEP * (float)m;
        e[m] = -d * d;
        mx = fmaxf(mx, e[m]);
    }
    float s = 0.0f, q = 0.0f;
#pragma unroll
    for (int m = 0; m < 8; m++) {
        float w = expf(e[m] - mx);
        s += w;
        q = fmaf(w, h[m], q);
    }
    g_reset[(size_t)b * FD + DD + u] = q / s;
}

// ---------------------------------------------------------------------------
// final: qk = tanh(dpre); ski = softmax; decay; outputs
// ---------------------------------------------------------------------------
__global__ void final_kernel(const float* __restrict__ state,
                             const float* __restrict__ elapsed,
                             float* __restrict__ out_h,
                             float* __restrict__ out_hh)
{
    int idx = blockIdx.x * blockDim.x + threadIdx.x;   // b*U + u
    if (idx >= BB * UU) return;
    int b = idx >> 9;
    int u = idx & 511;

    const float tau[8] = {1.0f, 3.1622776601683795f, 10.0f, 31.622776601683793f,
                          100.0f, 316.22776601683796f, 1000.0f, 3162.2776601683795f};

    float qk = tanhf(g_dpre[(size_t)b * UU + u]);

    const float* up = g_u + (size_t)b * RU + u * MM;
    float x[8];
    *(float4*)&x[0] = *(const float4*)(up);
    *(float4*)&x[4] = *(const float4*)(up + 4);

    const float* hp = state + (size_t)b * RU + u * MM;
    float h[8];
    *(float4*)&h[0] = *(const float4*)(hp);
    *(float4*)&h[4] = *(const float4*)(hp + 4);

    float e[8], mx = -1e30f;
#pragma unroll
    for (int m = 0; m < 8; m++) {
        float d = x[m] - LN_TAU_STEP * (float)m;
        e[m] = -d * d;
        mx = fmaxf(mx, e[m]);
    }
    float w[8], s = 0.0f;
#pragma unroll
    for (int m = 0; m < 8; m++) {
        w[m] = expf(e[m] - mx);
        s += w[m];
    }
    float inv_s = 1.0f / s;
    float el = elapsed[b];

    float hh[8], hn = 0.0f;
#pragma unroll
    for (int m = 0; m < 8; m++) {
        float ski = w[m] * inv_s;
        float dec = expf(-el / tau[m]);
        hh[m] = ((1.0f - ski) * h[m] + ski * qk) * dec;
        hn += hh[m];
    }

    float* op = out_hh + (size_t)b * RU + u * MM;
    *(float4*)(op)     = *(const float4*)&hh[0];
    *(float4*)(op + 4) = *(const float4*)&hh[4];
    if (out_h) out_h[(size_t)b * UU + u] = hn;
}

// ---------------------------------------------------------------------------
// launch
// ---------------------------------------------------------------------------
extern "C" void kernel_launch(void* const* d_in, const int* in_sizes, int n_in,
                              void* d_out, int out_size)
{
    const float* inputs  = (const float*)d_in[0];
    const float* elapsed = (const float*)d_in[1];
    const float* state   = (const float*)d_in[2];
    const float* W_r     = (const float*)d_in[3];
    const float* b_r     = (const float*)d_in[4];
    const float* W_d     = (const float*)d_in[5];
    const float* b_d     = (const float*)d_in[6];
    const float* W_u     = (const float*)d_in[7];
    const float* b_u     = (const float*)d_in[8];

    float* out = (float*)d_out;
    float* out_h;
    float* out_hh;
    if (out_size == BB * UU * MM) {          // only h_hat_next requested
        out_h = nullptr;
        out_hh = out;
    } else {                                  // (h_next, h_hat_next) flattened
        out_h = out;
        out_hh = out + (size_t)BB * UU;
    }

    float *p_fused, *p_reset, *p_r, *p_u, *p_dpre;
    cudaGetSymbolAddress((void**)&p_fused, g_fused);
    cudaGetSymbolAddress((void**)&p_reset, g_reset);
    cudaGetSymbolAddress((void**)&p_r,     g_r);
    cudaGetSymbolAddress((void**)&p_u,     g_u);
    cudaGetSymbolAddress((void**)&p_dpre,  g_dpre);

    const int ew_blocks = (BB * UU + 255) / 256;

    prep_kernel<<<ew_blocks, 256>>>(inputs, state);

    dim3 g1(RU / BN, BB / BM);    // 32 x 16
    sgemm_bias_kernel<<<g1, 256>>>(p_fused, W_r, b_r, p_r, BB, RU, FD);
    sgemm_bias_kernel<<<g1, 256>>>(p_fused, W_u, b_u, p_u, BB, RU, FD);

    gate_r_kernel<<<ew_blocks, 256>>>(state);

    dim3 g2(UU / BN, BB / BM);    // 4 x 16
    sgemm_bias_kernel<<<g2, 256>>>(p_reset, W_d, b_d, p_dpre, BB, UU, FD);

    final_kernel<<<ew_blocks, 256>>>(state, elapsed, out_h, out_hh);
}

// round 5
// speedup vs baseline: 2.6010x; 2.6010x over previous
#include <cuda_runtime.h>
#include <cuda_bf16.h>
#include <cstdint>
#include <math.h>

// ---------------------------------------------------------------------------
// CT-GRU cell: B=2048, U=512, M=8, D=512, fused=1024
// Round 3: HMMA (mma.sync bf16) split-precision GEMMs, K'=3072 = [hi|hi|lo]x[hi|lo|hi]
// (tcgen05 unavailable: harness PTX target is compute_103 base)
// ---------------------------------------------------------------------------

#define BB 2048
#define UU 512
#define MM 8
#define DD 512
#define FD 1024
#define RU 4096          // U*M
#define KTOT 3072        // 3 * FD (split-K)

#define LN_TAU_STEP 1.1512925464970229f

// ---------------- scratch (allocation-free device globals) -----------------
__device__ __nv_bfloat16 g_Af[(size_t)BB * KTOT];     // fused'  [B, 3072]
__device__ __nv_bfloat16 g_Ar[(size_t)BB * KTOT];     // reset'  [B, 3072]
__device__ __nv_bfloat16 g_Wr[(size_t)RU * KTOT];     // W_r'^T  [4096, 3072]
__device__ __nv_bfloat16 g_Wu[(size_t)RU * KTOT];     // W_u'^T  [4096, 3072]
__device__ __nv_bfloat16 g_Wd[(size_t)UU * KTOT];     // W_d'^T  [512, 3072]
__device__ float g_r[(size_t)BB * RU];                // ln_tau_r
__device__ float g_u[(size_t)BB * RU];                // ln_tau_s
__device__ float g_dpre[(size_t)BB * UU];             // pre-tanh

// ---------------------------- asm helpers ----------------------------------
__device__ __forceinline__ uint32_t smem_u32(const void* p) {
    uint32_t a;
    asm("{ .reg .u64 t; cvta.to.shared.u64 t, %1; cvt.u32.u64 %0, t; }"
        : "=r"(a) : "l"(p));
    return a;
}

__device__ __forceinline__ void ldsm_x4(uint32_t* r, uint32_t addr) {
    asm volatile("ldmatrix.sync.aligned.m8n8.x4.shared.b16 {%0,%1,%2,%3}, [%4];"
        : "=r"(r[0]), "=r"(r[1]), "=r"(r[2]), "=r"(r[3]) : "r"(addr));
}

__device__ __forceinline__ void mma_bf16(float* d, const uint32_t* a,
                                         uint32_t b0, uint32_t b1) {
    asm volatile("mma.sync.aligned.m16n8k16.row.col.f32.bf16.bf16.f32 "
        "{%0,%1,%2,%3}, {%4,%5,%6,%7}, {%8,%9}, {%0,%1,%2,%3};"
        : "+f"(d[0]), "+f"(d[1]), "+f"(d[2]), "+f"(d[3])
        : "r"(a[0]), "r"(a[1]), "r"(a[2]), "r"(a[3]), "r"(b0), "r"(b1));
}

__device__ __forceinline__ void cp16(uint32_t dst, const void* src) {
    asm volatile("cp.async.cg.shared.global [%0], [%1], 16;"
                 :: "r"(dst), "l"(src));
}
#define CP_COMMIT() asm volatile("cp.async.commit_group;" ::: "memory")
#define CP_WAIT(n)  asm volatile("cp.async.wait_group %0;" :: "n"(n) : "memory")

// ---------------------------------------------------------------------------
// prep: h = sum_m h_hat; write fused'=[x|h] and reset' inputs-part as bf16
// ---------------------------------------------------------------------------
__global__ void prep_kernel(const float* __restrict__ inputs,
                            const float* __restrict__ state)
{
    int idx = blockIdx.x * blockDim.x + threadIdx.x;
    if (idx >= BB * UU) return;
    int b = idx >> 9;
    int j = idx & 511;

    float x = inputs[(size_t)b * DD + j];
    __nv_bfloat16 xh = __float2bfloat16_rn(x);
    __nv_bfloat16 xl = __float2bfloat16_rn(x - __bfloat162float(xh));

    size_t base = (size_t)b * KTOT;
    g_Af[base + j]        = xh;
    g_Af[base + 1024 + j] = xh;
    g_Af[base + 2048 + j] = xl;
    g_Ar[base + j]        = xh;
    g_Ar[base + 1024 + j] = xh;
    g_Ar[base + 2048 + j] = xl;

    const float* hp = state + (size_t)b * RU + j * MM;
    float4 h0 = *(const float4*)(hp);
    float4 h1 = *(const float4*)(hp + 4);
    float h = ((h0.x + h0.y) + (h0.z + h0.w)) + ((h1.x + h1.y) + (h1.z + h1.w));
    __nv_bfloat16 hh = __float2bfloat16_rn(h);
    __nv_bfloat16 hl = __float2bfloat16_rn(h - __bfloat162float(hh));
    g_Af[base + 512 + j]        = hh;
    g_Af[base + 1024 + 512 + j] = hh;
    g_Af[base + 2048 + 512 + j] = hl;
}

// ---------------------------------------------------------------------------
// weight convert + transpose: W[1024, Ndim] fp32 -> Wt[Ndim, 3072] bf16
// segments [hi | lo | hi]
// ---------------------------------------------------------------------------
__global__ void wconv_kernel(const float* __restrict__ W,
                             __nv_bfloat16* __restrict__ Wt, int Ndim)
{
    __shared__ float t[32][33];
    int n0 = blockIdx.x * 32;
    int k0 = blockIdx.y * 32;
    int tx = threadIdx.x, ty = threadIdx.y;

#pragma unroll
    for (int i = 0; i < 4; i++) {
        int k = k0 + ty + i * 8;
        t[ty + i * 8][tx] = W[(size_t)k * Ndim + n0 + tx];
    }
    __syncthreads();

#pragma unroll
    for (int i = 0; i < 4; i++) {
        int r = ty + i * 8;
        float v = t[tx][r];
        __nv_bfloat16 vh = __float2bfloat16_rn(v);
        __nv_bfloat16 vl = __float2bfloat16_rn(v - __bfloat162float(vh));
        size_t base = (size_t)(n0 + r) * KTOT + k0 + tx;
        Wt[base]        = vh;
        Wt[base + 1024] = vl;
        Wt[base + 2048] = vh;
    }
}

// ---------------------------------------------------------------------------
// HMMA GEMM: C[2048, Ndim] = A'[2048,3072] @ Bt'[Ndim,3072]^T + bias
// BM=256, BN=128, BK=64, 512 threads (16 warps, 4x4), warp tile 64x32.
// Double-buffered cp.async stages; XOR-swizzled 128B rows for ldmatrix.
// ---------------------------------------------------------------------------
#define GBM 256
#define GBN 128
#define GBK 64
#define NIT (KTOT / GBK)              // 48
#define STG_A 32768u                  // 256 * 128B
#define STG_B 16384u                  // 128 * 128B
#define STG   (STG_A + STG_B)         // 49152
#define GEMM_SMEM (2u * STG)          // 98304

// swizzled byte offset within a tile of 128B rows
__device__ __forceinline__ uint32_t swz(int row, int chunk) {
    return (uint32_t)(row * 128 + ((chunk ^ (row & 7)) << 4));
}

__global__ void __launch_bounds__(512, 1)
gemm_mma_kernel(const __nv_bfloat16* __restrict__ A,
                const __nv_bfloat16* __restrict__ Bt,
                const float* __restrict__ bias,
                float* __restrict__ C,
                int Ndim)
{
    extern __shared__ char smem[];
    const uint32_t sb = smem_u32(smem);
    const int tid = threadIdx.x;
    const int wid = tid >> 5;
    const int lane = tid & 31;
    const int bn = blockIdx.x * GBN;
    const int bm = blockIdx.y * GBM;

    const int warp_m = (wid & 3) * 64;      // 0,64,128,192
    const int warp_n = (wid >> 2) * 32;     // 0,32,64,96

    float acc[4][4][4];
#pragma unroll
    for (int i = 0; i < 4; i++)
#pragma unroll
        for (int j = 0; j < 4; j++)
#pragma unroll
            for (int v = 0; v < 4; v++) acc[i][j][v] = 0.0f;

    // ---- stage loader: 3072 granules of 16B, 6 per thread ----
    auto load_stage = [&](int it, int buf) {
        const int k0 = it * GBK;
        const uint32_t abase = sb + (uint32_t)buf * STG;
        const uint32_t bbase = abase + STG_A;
#pragma unroll
        for (int g = tid; g < 3072; g += 512) {
            if (g < 2048) {
                int row = g >> 3, ch = g & 7;
                cp16(abase + swz(row, ch),
                     A + (size_t)(bm + row) * KTOT + k0 + ch * 8);
            } else {
                int g2 = g - 2048;
                int row = g2 >> 3, ch = g2 & 7;
                cp16(bbase + swz(row, ch),
                     Bt + (size_t)(bn + row) * KTOT + k0 + ch * 8);
            }
        }
        CP_COMMIT();
    };

    load_stage(0, 0);

#pragma unroll 1
    for (int it = 0; it < NIT; it++) {
        if (it + 1 < NIT) load_stage(it + 1, (it + 1) & 1);
        if (it + 1 < NIT) { CP_WAIT(1); } else { CP_WAIT(0); }
        __syncthreads();

        const uint32_t abase = sb + (uint32_t)(it & 1) * STG;
        const uint32_t bbase = abase + STG_A;

#pragma unroll
        for (int kk = 0; kk < 4; kk++) {            // k-steps of 16
            const int kch = kk * 2;                 // 16B-chunk index of k0
            uint32_t a[4][4];
#pragma unroll
            for (int mi = 0; mi < 4; mi++) {
                int row = warp_m + mi * 16 + (lane & 15);
                int ch = kch + ((lane >> 4) & 1);
                ldsm_x4(a[mi], abase + swz(row, ch));
            }
#pragma unroll
            for (int nb = 0; nb < 2; nb++) {
                uint32_t b[4];
                int row = warp_n + nb * 16 + (lane & 7) + (((lane >> 4) & 1) << 3);
                int ch = kch + ((lane >> 3) & 1);
                ldsm_x4(b, bbase + swz(row, ch));
#pragma unroll
                for (int mi = 0; mi < 4; mi++) {
                    mma_bf16(acc[mi][nb * 2 + 0], a[mi], b[0], b[1]);
                    mma_bf16(acc[mi][nb * 2 + 1], a[mi], b[2], b[3]);
                }
            }
        }
        __syncthreads();
    }

    // ---- epilogue with bias ----
#pragma unroll
    for (int ni = 0; ni < 4; ni++) {
        int col = bn + warp_n + ni * 8 + (lane & 3) * 2;
        float bv0 = bias[col], bv1 = bias[col + 1];
#pragma unroll
        for (int mi = 0; mi < 4; mi++) {
            int r0 = bm + warp_m + mi * 16 + (lane >> 2);
            float2 v0 = make_float2(acc[mi][ni][0] + bv0, acc[mi][ni][1] + bv1);
            float2 v1 = make_float2(acc[mi][ni][2] + bv0, acc[mi][ni][3] + bv1);
            *(float2*)(C + (size_t)r0 * Ndim + col) = v0;
            *(float2*)(C + (size_t)(r0 + 8) * Ndim + col) = v1;
        }
    }
}

// ---------------------------------------------------------------------------
// gate_r: rki softmax + q_input; writes q (bf16 split) into reset' columns
// ---------------------------------------------------------------------------
__global__ void gate_r_kernel(const float* __restrict__ state)
{
    int idx = blockIdx.x * blockDim.x + threadIdx.x;
    if (idx >= BB * UU) return;
    int b = idx >> 9;
    int u = idx & 511;

    const float* rp = g_r + (size_t)b * RU + u * MM;
    float x[8];
    *(float4*)&x[0] = *(const float4*)(rp);
    *(float4*)&x[4] = *(const float4*)(rp + 4);

    const float* hp = state + (size_t)b * RU + u * MM;
    float h[8];
    *(float4*)&h[0] = *(const float4*)(hp);
    *(float4*)&h[4] = *(const float4*)(hp + 4);

    float e[8], mx = -1e30f;
#pragma unroll
    for (int m = 0; m < 8; m++) {
        float d = x[m] - LN_TAU_STEP * (float)m;
        e[m] = -d * d;
        mx = fmaxf(mx, e[m]);
    }
    float s = 0.0f, q = 0.0f;
#pragma unroll
    for (int m = 0; m < 8; m++) {
        float w = expf(e[m] - mx);
        s += w;
        q = fmaf(w, h[m], q);
    }
    float qv = q / s;
    __nv_bfloat16 qh = __float2bfloat16_rn(qv);
    __nv_bfloat16 ql = __float2bfloat16_rn(qv - __bfloat162float(qh));
    size_t base = (size_t)b * KTOT;
    g_Ar[base + 512 + u]        = qh;
    g_Ar[base + 1024 + 512 + u] = qh;
    g_Ar[base + 2048 + 512 + u] = ql;
}

// ---------------------------------------------------------------------------
// final: qk = tanh(dpre); ski softmax; decay; outputs
// ---------------------------------------------------------------------------
__global__ void final_kernel(const float* __restrict__ state,
                             const float* __restrict__ elapsed,
                             float* __restrict__ out_h,
                             float* __restrict__ out_hh)
{
    int idx = blockIdx.x * blockDim.x + threadIdx.x;
    if (idx >= BB * UU) return;
    int b = idx >> 9;
    int u = idx & 511;

    const float tau[8] = {1.0f, 3.1622776601683795f, 10.0f, 31.622776601683793f,
                          100.0f, 316.22776601683796f, 1000.0f, 3162.2776601683795f};

    float qk = tanhf(g_dpre[(size_t)b * UU + u]);

    const float* up = g_u + (size_t)b * RU + u * MM;
    float x[8];
    *(float4*)&x[0] = *(const float4*)(up);
    *(float4*)&x[4] = *(const float4*)(up + 4);

    const float* hp = state + (size_t)b * RU + u * MM;
    float h[8];
    *(float4*)&h[0] = *(const float4*)(hp);
    *(float4*)&h[4] = *(const float4*)(hp + 4);

    float e[8], mx = -1e30f;
#pragma unroll
    for (int m = 0; m < 8; m++) {
        float d = x[m] - LN_TAU_STEP * (float)m;
        e[m] = -d * d;
        mx = fmaxf(mx, e[m]);
    }
    float w[8], s = 0.0f;
#pragma unroll
    for (int m = 0; m < 8; m++) {
        w[m] = expf(e[m] - mx);
        s += w[m];
    }
    float inv_s = 1.0f / s;
    float el = elapsed[b];

    float hh[8], hn = 0.0f;
#pragma unroll
    for (int m = 0; m < 8; m++) {
        float ski = w[m] * inv_s;
        float dec = expf(-el / tau[m]);
        hh[m] = ((1.0f - ski) * h[m] + ski * qk) * dec;
        hn += hh[m];
    }

    float* op = out_hh + (size_t)b * RU + u * MM;
    *(float4*)(op)     = *(const float4*)&hh[0];
    *(float4*)(op + 4) = *(const float4*)&hh[4];
    if (out_h) out_h[(size_t)b * UU + u] = hn;
}

// ---------------------------------------------------------------------------
// launch
// ---------------------------------------------------------------------------
extern "C" void kernel_launch(void* const* d_in, const int* in_sizes, int n_in,
                              void* d_out, int out_size)
{
    const float* inputs  = (const float*)d_in[0];
    const float* elapsed = (const float*)d_in[1];
    const float* state   = (const float*)d_in[2];
    const float* W_r     = (const float*)d_in[3];
    const float* b_r     = (const float*)d_in[4];
    const float* W_d     = (const float*)d_in[5];
    const float* b_d     = (const float*)d_in[6];
    const float* W_u     = (const float*)d_in[7];
    const float* b_u     = (const float*)d_in[8];

    float* out = (float*)d_out;
    float* out_h;
    float* out_hh;
    if (out_size == BB * UU * MM) {
        out_h = nullptr;
        out_hh = out;
    } else {
        out_h = out;
        out_hh = out + (size_t)BB * UU;
    }

    __nv_bfloat16 *p_Af, *p_Ar, *p_Wr, *p_Wu, *p_Wd;
    float *p_r, *p_u, *p_dpre;
    cudaGetSymbolAddress((void**)&p_Af, g_Af);
    cudaGetSymbolAddress((void**)&p_Ar, g_Ar);
    cudaGetSymbolAddress((void**)&p_Wr, g_Wr);
    cudaGetSymbolAddress((void**)&p_Wu, g_Wu);
    cudaGetSymbolAddress((void**)&p_Wd, g_Wd);
    cudaGetSymbolAddress((void**)&p_r,    g_r);
    cudaGetSymbolAddress((void**)&p_u,    g_u);
    cudaGetSymbolAddress((void**)&p_dpre, g_dpre);

    cudaFuncSetAttribute(gemm_mma_kernel,
                         cudaFuncAttributeMaxDynamicSharedMemorySize, GEMM_SMEM);

    const int ew_blocks = (BB * UU + 255) / 256;
    dim3 tb(32, 8);

    prep_kernel<<<ew_blocks, 256>>>(inputs, state);
    wconv_kernel<<<dim3(RU / 32, 32), tb>>>(W_r, p_Wr, RU);
    wconv_kernel<<<dim3(RU / 32, 32), tb>>>(W_u, p_Wu, RU);
    wconv_kernel<<<dim3(UU / 32, 32), tb>>>(W_d, p_Wd, UU);

    gemm_mma_kernel<<<dim3(RU / GBN, BB / GBM), 512, GEMM_SMEM>>>(p_Af, p_Wr, b_r, p_r, RU);
    gemm_mma_kernel<<<dim3(RU / GBN, BB / GBM), 512, GEMM_SMEM>>>(p_Af, p_Wu, b_u, p_u, RU);

    gate_r_kernel<<<ew_blocks, 256>>>(state);

    gemm_mma_kernel<<<dim3(UU / GBN, BB / GBM), 512, GEMM_SMEM>>>(p_Ar, p_Wd, b_d, p_dpre, UU);

    final_kernel<<<ew_blocks, 256>>>(state, elapsed, out_h, out_hh);
}